// round 1
// baseline (speedup 1.0000x reference)
#include <cuda_runtime.h>
#include <cuda_bf16.h>
#include <math.h>

// Problem constants
#define BB 32
#define TT 2048
#define EE 1024
#define AA 1024
#define DD 1024

// Scratch (no cudaMalloc allowed)
__device__ float g_dp[BB * AA];        // dec_proj + b_enc  [B, A]
__device__ float g_energy[BB * TT];    // energy (pre-softmax) [B, T]

// ---------------------------------------------------------------------------
// 0) zero scratch energy + context output region
// ---------------------------------------------------------------------------
__global__ void zero_kernel(float* __restrict__ energy, float* __restrict__ ctx) {
    int i = blockIdx.x * blockDim.x + threadIdx.x;
    if (i < BB * TT) energy[i] = 0.0f;
    if (i < BB * EE) ctx[i] = 0.0f;
}

// ---------------------------------------------------------------------------
// 1) dec_proj[b,a] = b_enc[a] + sum_d dec_out[b,d] * W_dec[d,a]
//    grid = (B), 256 threads, each thread 4 output columns
// ---------------------------------------------------------------------------
__global__ void dec_proj_kernel(const float* __restrict__ dec,
                                const float* __restrict__ Wdec,
                                const float* __restrict__ b_enc,
                                float* __restrict__ dp) {
    int b = blockIdx.x;
    __shared__ float ds[DD];
    for (int i = threadIdx.x; i < DD; i += 256) ds[i] = dec[b * DD + i];
    __syncthreads();

    #pragma unroll
    for (int j = 0; j < 4; j++) {
        int a = threadIdx.x + j * 256;
        float s = b_enc[a];
        #pragma unroll 4
        for (int d = 0; d < DD; d++) {
            s = fmaf(ds[d], Wdec[(size_t)d * AA + a], s);
        }
        dp[b * AA + a] = s;
    }
}

// ---------------------------------------------------------------------------
// 2) fused GEMM + tanh + v-dot:
//    energy[row] += sum_{n in tile} v[n] * tanh( (enc @ W_enc)[row,n] + dp[b,n] )
//    128x128x8 tile, 256 threads, 8x8 per-thread microtile
// ---------------------------------------------------------------------------
#define BM 128
#define BN 128
#define BKK 8

__global__ __launch_bounds__(256, 2)
void energy_gemm_kernel(const float* __restrict__ enc,
                        const float* __restrict__ Wenc,
                        const float* __restrict__ dp,
                        const float* __restrict__ v,
                        float* __restrict__ energy) {
    __shared__ float As[BKK][BM];
    __shared__ float Bs[BKK][BN];
    __shared__ float red[BM][17];   // row-partial reduction across 16 x-threads

    int tid = threadIdx.x;
    int tx = tid & 15;
    int ty = tid >> 4;

    int rowBase = blockIdx.y * BM;        // global M row base
    int colBase = blockIdx.x * BN;        // global N (A-dim) base
    int b = rowBase / TT;                 // BM=128 divides T=2048 -> single batch per tile

    float acc[8][8];
    #pragma unroll
    for (int i = 0; i < 8; i++)
        #pragma unroll
        for (int j = 0; j < 8; j++) acc[i][j] = 0.0f;

    // A tile load map: 256 threads, each one float4 of a [128 x 8] tile
    int aRow = tid >> 1;              // 0..127
    int aCol = (tid & 1) * 4;         // 0 or 4
    // B tile load map: [8 x 128] tile, each thread one float4
    int bRow = tid >> 5;              // 0..7
    int bCol = (tid & 31) * 4;        // 0..124

    const float* Aptr = enc + (size_t)(rowBase + aRow) * EE + aCol;
    const float* Bptr = Wenc + (size_t)bRow * AA + colBase + bCol;

    for (int k0 = 0; k0 < EE; k0 += BKK) {
        float4 av = *(const float4*)(Aptr + k0);
        As[aCol + 0][aRow] = av.x;
        As[aCol + 1][aRow] = av.y;
        As[aCol + 2][aRow] = av.z;
        As[aCol + 3][aRow] = av.w;
        *(float4*)&Bs[bRow][bCol] = *(const float4*)(Bptr + (size_t)k0 * AA);
        __syncthreads();

        #pragma unroll
        for (int k = 0; k < BKK; k++) {
            float4 a0 = *(const float4*)&As[k][ty * 8];
            float4 a1 = *(const float4*)&As[k][ty * 8 + 4];
            float4 b0 = *(const float4*)&Bs[k][tx * 8];
            float4 b1 = *(const float4*)&Bs[k][tx * 8 + 4];
            float ar[8] = {a0.x, a0.y, a0.z, a0.w, a1.x, a1.y, a1.z, a1.w};
            float br[8] = {b0.x, b0.y, b0.z, b0.w, b1.x, b1.y, b1.z, b1.w};
            #pragma unroll
            for (int i = 0; i < 8; i++)
                #pragma unroll
                for (int j = 0; j < 8; j++)
                    acc[i][j] = fmaf(ar[i], br[j], acc[i][j]);
        }
        __syncthreads();
    }

    // Epilogue: tanh(acc + dp) * v, reduce over this tile's 8 columns
    float vv[8], dpv[8];
    #pragma unroll
    for (int j = 0; j < 8; j++) {
        int col = colBase + tx * 8 + j;
        vv[j] = v[col];
        dpv[j] = dp[b * AA + col];
    }

    #pragma unroll
    for (int i = 0; i < 8; i++) {
        float s = 0.0f;
        #pragma unroll
        for (int j = 0; j < 8; j++) {
            float e = tanhf(acc[i][j] + dpv[j]);
            s = fmaf(e, vv[j], s);
        }
        red[ty * 8 + i][tx] = s;
    }
    __syncthreads();

    // 128 threads each reduce their row's 16 partials, accumulate into energy
    if (tid < BM) {
        float s = 0.0f;
        #pragma unroll
        for (int x = 0; x < 16; x++) s += red[tid][x];
        atomicAdd(&energy[(size_t)rowBase + tid], s);
    }
}

// ---------------------------------------------------------------------------
// 3) masked softmax per batch row.  mask is 0/1 MULTIPLY (masked logits -> 0)
//    att[b,t] = softmax(energy[b,:] * mask)[t]
// ---------------------------------------------------------------------------
__global__ void softmax_kernel(const float* __restrict__ energy,
                               const int* __restrict__ x_lens,
                               float* __restrict__ att) {
    int b = blockIdx.x;
    int tid = threadIdx.x;
    int len = x_lens[b];
    __shared__ float sh[256];

    float e[8];
    float mx = -1e30f;
    #pragma unroll
    for (int j = 0; j < 8; j++) {
        int t = tid + j * 256;
        float val = energy[b * TT + t];
        val = (t < len) ? val : 0.0f;   // multiply-mask semantics
        e[j] = val;
        mx = fmaxf(mx, val);
    }
    sh[tid] = mx;
    __syncthreads();
    for (int s = 128; s > 0; s >>= 1) {
        if (tid < s) sh[tid] = fmaxf(sh[tid], sh[tid + s]);
        __syncthreads();
    }
    mx = sh[0];
    __syncthreads();

    float sum = 0.0f;
    #pragma unroll
    for (int j = 0; j < 8; j++) {
        e[j] = expf(e[j] - mx);
        sum += e[j];
    }
    sh[tid] = sum;
    __syncthreads();
    for (int s = 128; s > 0; s >>= 1) {
        if (tid < s) sh[tid] += sh[tid + s];
        __syncthreads();
    }
    float inv = 1.0f / sh[0];

    #pragma unroll
    for (int j = 0; j < 8; j++) {
        int t = tid + j * 256;
        att[b * TT + t] = e[j] * inv;
    }
}

// ---------------------------------------------------------------------------
// 4) context[b,e] = sum_t att[b,t] * enc[b,t,e]
//    grid (B, 16): each block handles 128 t-rows, 256 threads x 4 e each
// ---------------------------------------------------------------------------
__global__ void context_kernel(const float* __restrict__ enc,
                               const float* __restrict__ att,
                               float* __restrict__ ctx) {
    int b = blockIdx.x;
    int t0 = blockIdx.y * 128;
    int tid = threadIdx.x;

    __shared__ float ws[128];
    if (tid < 128) ws[tid] = att[b * TT + t0 + tid];
    __syncthreads();

    float acc[4] = {0.0f, 0.0f, 0.0f, 0.0f};
    for (int t = 0; t < 128; t++) {
        float w = ws[t];
        const float* row = enc + ((size_t)(b * TT + t0 + t)) * EE;
        #pragma unroll
        for (int j = 0; j < 4; j++)
            acc[j] = fmaf(w, row[tid + j * 256], acc[j]);
    }
    #pragma unroll
    for (int j = 0; j < 4; j++)
        atomicAdd(&ctx[b * EE + tid + j * 256], acc[j]);
}

// ---------------------------------------------------------------------------
// launch
// ---------------------------------------------------------------------------
extern "C" void kernel_launch(void* const* d_in, const int* in_sizes, int n_in,
                              void* d_out, int out_size) {
    const float* enc_out = (const float*)d_in[0];   // [B,T,E]
    const int*   x_lens  = (const int*)  d_in[1];   // [B]
    const float* dec_out = (const float*)d_in[2];   // [B,1,D]
    // d_in[3] = att_weights_step (unused by reference)
    const float* W_enc   = (const float*)d_in[4];   // [E,A]
    const float* b_enc   = (const float*)d_in[5];   // [A]
    const float* W_dec   = (const float*)d_in[6];   // [D,A]
    const float* v       = (const float*)d_in[7];   // [A]

    float* out = (float*)d_out;
    float* ctx = out;                 // [B,1,E] = 32768 floats
    float* att = out + BB * EE;       // [B,T]   = 65536 floats

    float* dp;
    float* energy;
    cudaGetSymbolAddress((void**)&dp, g_dp);
    cudaGetSymbolAddress((void**)&energy, g_energy);

    // 0) zero energy scratch + context output region
    zero_kernel<<<(BB * TT + 255) / 256, 256>>>(energy, ctx);

    // 1) dec projection
    dec_proj_kernel<<<BB, 256>>>(dec_out, W_dec, b_enc, dp);

    // 2) fused GEMM + tanh + v-dot -> energy
    dim3 grid(AA / BN, (BB * TT) / BM);   // (8, 512)
    energy_gemm_kernel<<<grid, 256>>>(enc_out, W_enc, dp, v, energy);

    // 3) masked softmax -> att (written straight to output)
    softmax_kernel<<<BB, 256>>>(energy, x_lens, att);

    // 4) context vector
    dim3 cgrid(BB, 16);
    context_kernel<<<cgrid, 256>>>(enc_out, att, ctx);
}

// round 7
// speedup vs baseline: 2.3595x; 2.3595x over previous
#include <cuda_runtime.h>
#include <cuda_bf16.h>
#include <math.h>
#include <stdint.h>

// Problem constants
#define BB 32
#define TT 2048
#define EE 1024
#define AA 1024
#define DD 1024
#define MROWS (BB * TT)   // 65536

// ---------------------------------------------------------------------------
// Scratch (__device__ globals; no cudaMalloc allowed)
// ---------------------------------------------------------------------------
__device__ __nv_bfloat16 g_encsplit[(size_t)MROWS * 2048]; // [row, 0:1024]=hi, [1024:2048]=lo
__device__ __nv_bfloat16 g_wsplit[(size_t)AA * 2048];      // [a, 0:1024]=W^T hi, [1024:2048]=lo
__device__ float g_dp[BB * AA];                            // dec_proj + b_enc
__device__ float g_energy[BB * TT];                        // pre-softmax energy

// ---------------------------------------------------------------------------
// PTX helpers (base-target-safe only: cp.async / ldmatrix / mma.sync)
// ---------------------------------------------------------------------------
__device__ __forceinline__ uint32_t smem_u32(const void* p) {
    uint32_t a;
    asm("{ .reg .u64 t; cvta.to.shared.u64 t, %1; cvt.u32.u64 %0, t; }" : "=r"(a) : "l"(p));
    return a;
}

__device__ __forceinline__ void cp_async16(uint32_t dst, const void* src) {
    asm volatile("cp.async.cg.shared.global [%0], [%1], 16;\n" :: "r"(dst), "l"(src));
}
#define CP_COMMIT() asm volatile("cp.async.commit_group;\n" ::: "memory")
#define CP_WAIT2()  asm volatile("cp.async.wait_group 2;\n" ::: "memory")

__device__ __forceinline__ void ldm_x4(uint32_t& r0, uint32_t& r1, uint32_t& r2, uint32_t& r3,
                                       uint32_t addr) {
    asm volatile("ldmatrix.sync.aligned.m8n8.x4.shared.b16 {%0,%1,%2,%3}, [%4];"
                 : "=r"(r0), "=r"(r1), "=r"(r2), "=r"(r3) : "r"(addr));
}

__device__ __forceinline__ void mma_bf16(float* c, uint32_t a0, uint32_t a1, uint32_t a2,
                                         uint32_t a3, uint32_t b0, uint32_t b1) {
    asm volatile(
        "mma.sync.aligned.m16n8k16.row.col.f32.bf16.bf16.f32 "
        "{%0,%1,%2,%3}, {%4,%5,%6,%7}, {%8,%9}, {%0,%1,%2,%3};"
        : "+f"(c[0]), "+f"(c[1]), "+f"(c[2]), "+f"(c[3])
        : "r"(a0), "r"(a1), "r"(a2), "r"(a3), "r"(b0), "r"(b1));
}

// ---------------------------------------------------------------------------
// 0) zero energy scratch + context output region
// ---------------------------------------------------------------------------
__global__ void zero_kernel(float* __restrict__ energy, float* __restrict__ ctx) {
    int i = blockIdx.x * blockDim.x + threadIdx.x;
    if (i < BB * TT) energy[i] = 0.0f;
    if (i < BB * EE) ctx[i] = 0.0f;
}

// ---------------------------------------------------------------------------
// 1) split enc_out into bf16 hi/lo
// ---------------------------------------------------------------------------
__global__ void split_enc_kernel(const float* __restrict__ enc) {
    int row = blockIdx.x;
    int tid = threadIdx.x;  // 0..255
    float4 x = ((const float4*)(enc + (size_t)row * EE))[tid];
    union { __nv_bfloat16 h[4]; uint2 u; } hi, lo;
    float xs[4] = {x.x, x.y, x.z, x.w};
    #pragma unroll
    for (int k = 0; k < 4; k++) {
        __nv_bfloat16 h = __float2bfloat16(xs[k]);
        hi.h[k] = h;
        lo.h[k] = __float2bfloat16(xs[k] - __bfloat162float(h));
    }
    __nv_bfloat16* base = g_encsplit + (size_t)row * 2048;
    *(uint2*)(base + tid * 4)        = hi.u;
    *(uint2*)(base + 1024 + tid * 4) = lo.u;
}

// ---------------------------------------------------------------------------
// 2) split + transpose W_enc: g_wsplit[a, e] = bf16split(W_enc[e, a])
// ---------------------------------------------------------------------------
__global__ void split_w_kernel(const float* __restrict__ W) {
    __shared__ float tile[32][33];
    int e0 = blockIdx.x * 32, a0 = blockIdx.y * 32;
    int tx = threadIdx.x, ty = threadIdx.y;  // 32 x 8
    #pragma unroll
    for (int k = 0; k < 4; k++) {
        int e = ty + k * 8;
        tile[e][tx] = W[(size_t)(e0 + e) * AA + a0 + tx];
    }
    __syncthreads();
    #pragma unroll
    for (int k = 0; k < 4; k++) {
        int a = ty + k * 8;
        float val = tile[tx][a];
        __nv_bfloat16 h = __float2bfloat16(val);
        __nv_bfloat16 l = __float2bfloat16(val - __bfloat162float(h));
        __nv_bfloat16* base = g_wsplit + (size_t)(a0 + a) * 2048;
        base[e0 + tx] = h;
        base[1024 + e0 + tx] = l;
    }
}

// ---------------------------------------------------------------------------
// 3) dec_proj[b,a] = b_enc[a] + sum_d dec[b,d] * W_dec[d,a]
// ---------------------------------------------------------------------------
__global__ void dec_proj_kernel(const float* __restrict__ dec,
                                const float* __restrict__ Wdec,
                                const float* __restrict__ b_enc,
                                float* __restrict__ dp) {
    int c0 = blockIdx.x * 8;
    int bq = threadIdx.x >> 3;
    int j = threadIdx.x & 7;
    __shared__ float dsm[32 * 64];
    float s = b_enc[c0 + j];
    for (int d0 = 0; d0 < DD; d0 += 64) {
        for (int ii = threadIdx.x; ii < 2048; ii += 256) {
            int bb2 = ii >> 6, dd2 = ii & 63;
            dsm[ii] = dec[bb2 * DD + d0 + dd2];
        }
        __syncthreads();
        #pragma unroll 8
        for (int d = 0; d < 64; d++)
            s = fmaf(dsm[bq * 64 + d], Wdec[(size_t)(d0 + d) * AA + c0 + j], s);
        __syncthreads();
    }
    dp[bq * AA + c0 + j] = s;
}

// ---------------------------------------------------------------------------
// 4) mma.sync bf16-split GEMM + tanh + v-dot -> energy
//    CTA 128x128, 8 warps (2x4), warp 64x32, BK=32, 4-stage cp.async
//    Concatenated K = 3*1024 (A: hi,hi,lo  x  W: hi,lo,hi)
// ---------------------------------------------------------------------------
#define BKC 32
#define ROWB 80             // padded smem row stride (bytes) for 32 bf16
#define STG_A (128 * ROWB)  // 10240
#define STG   (2 * STG_A)   // 20480 per stage (A then B)
#define NSTAGE 4
#define GEMM_SMEM (NSTAGE * STG)   // 81920
#define NCHUNK 96

__device__ __forceinline__ void load_stage(int chunk, uint32_t aT, uint32_t bT,
                                           int rowBase, int colBase, int tid) {
    int phase = chunk >> 5;       // 0,1,2
    int j = chunk & 31;
    int aOff = ((phase == 2) ? 1024 : 0) + j * 32;   // elements
    int bOff = ((phase == 1) ? 1024 : 0) + j * 32;
    const char* aSrc = (const char*)g_encsplit + (size_t)rowBase * 4096 + (size_t)aOff * 2;
    const char* bSrc = (const char*)g_wsplit  + (size_t)colBase * 4096 + (size_t)bOff * 2;
    // A: 128 rows x 4 chunks of 16B
    #pragma unroll
    for (int k = 0; k < 2; k++) {
        int t = tid + k * 256;
        int r = t >> 2, sg = t & 3;
        cp_async16(aT + r * ROWB + sg * 16, aSrc + (size_t)r * 4096 + sg * 16);
    }
    // B: 128 rows x 4 chunks of 16B
    #pragma unroll
    for (int k = 0; k < 2; k++) {
        int t = tid + k * 256;
        int r = t >> 2, sg = t & 3;
        cp_async16(bT + r * ROWB + sg * 16, bSrc + (size_t)r * 4096 + sg * 16);
    }
}

__global__ __launch_bounds__(256, 2)
void energy_gemm_mma(const float* __restrict__ dp,
                     const float* __restrict__ v,
                     float* __restrict__ energy) {
    extern __shared__ char smem[];
    uint32_t sb = smem_u32(smem);
    int tid = threadIdx.x;
    int lane = tid & 31;
    int w = tid >> 5;
    int wm = w >> 2;          // 0..1  (64 rows each)
    int wn = w & 3;           // 0..3  (32 cols each)
    int rowBase = blockIdx.y * 128;
    int colBase = blockIdx.x * 128;
    int b = rowBase >> 11;

    float acc[4][4][4];       // [mt][nt][reg]
    #pragma unroll
    for (int i = 0; i < 4; i++)
        #pragma unroll
        for (int jj = 0; jj < 4; jj++)
            #pragma unroll
            for (int r = 0; r < 4; r++) acc[i][jj][r] = 0.0f;

    // Prologue: 3 stages in flight
    #pragma unroll
    for (int s = 0; s < NSTAGE - 1; s++) {
        load_stage(s, sb + s * STG, sb + s * STG + STG_A, rowBase, colBase, tid);
        CP_COMMIT();
    }

    // ldmatrix base addresses (relative to stage base)
    uint32_t aAddrOff = (uint32_t)((wm * 64 + (lane & 15)) * ROWB + ((lane >> 4) & 1) * 16);
    uint32_t bAddrOff = (uint32_t)((wn * 32 + (lane & 7) + ((lane >> 4) & 1) * 8) * ROWB
                                   + ((lane >> 3) & 1) * 16);

    for (int i = 0; i < NCHUNK; i++) {
        CP_WAIT2();
        __syncthreads();
        int stage = i & (NSTAGE - 1);
        uint32_t As = sb + stage * STG;
        uint32_t Bs = As + STG_A;

        #pragma unroll
        for (int ks = 0; ks < 2; ks++) {
            uint32_t af[4][4];
            #pragma unroll
            for (int mt = 0; mt < 4; mt++)
                ldm_x4(af[mt][0], af[mt][1], af[mt][2], af[mt][3],
                       As + aAddrOff + mt * 16 * ROWB + ks * 32);
            uint32_t bf[2][4];   // [nt-pair][reg]: regs {0,1}=nt even, {2,3}=nt odd
            #pragma unroll
            for (int np = 0; np < 2; np++)
                ldm_x4(bf[np][0], bf[np][1], bf[np][2], bf[np][3],
                       Bs + bAddrOff + np * 16 * ROWB + ks * 32);
            #pragma unroll
            for (int mt = 0; mt < 4; mt++) {
                #pragma unroll
                for (int nt = 0; nt < 4; nt++) {
                    uint32_t b0 = bf[nt >> 1][(nt & 1) * 2 + 0];
                    uint32_t b1 = bf[nt >> 1][(nt & 1) * 2 + 1];
                    mma_bf16(acc[mt][nt], af[mt][0], af[mt][1], af[mt][2], af[mt][3], b0, b1);
                }
            }
        }
        __syncthreads();
        if (i + NSTAGE - 1 < NCHUNK) {
            int ns = (i + NSTAGE - 1) & (NSTAGE - 1);
            load_stage(i + NSTAGE - 1, sb + ns * STG, sb + ns * STG + STG_A,
                       rowBase, colBase, tid);
        }
        CP_COMMIT();
    }
    __syncthreads();

    // Epilogue: s[row] = sum_col v[col] * tanh(acc + dp[col]); quad shfl-reduce
    float* red = (float*)smem;    // [128][4]
    #pragma unroll
    for (int mt = 0; mt < 4; mt++) {
        float s0 = 0.0f, s1 = 0.0f;
        #pragma unroll
        for (int nt = 0; nt < 4; nt++) {
            int col = colBase + wn * 32 + nt * 8 + (lane & 3) * 2;
            float d0 = dp[b * AA + col], d1 = dp[b * AA + col + 1];
            float v0 = v[col], v1 = v[col + 1];
            s0 = fmaf(v0, tanhf(acc[mt][nt][0] + d0), s0);
            s0 = fmaf(v1, tanhf(acc[mt][nt][1] + d1), s0);
            s1 = fmaf(v0, tanhf(acc[mt][nt][2] + d0), s1);
            s1 = fmaf(v1, tanhf(acc[mt][nt][3] + d1), s1);
        }
        s0 += __shfl_xor_sync(0xFFFFFFFF, s0, 1);
        s0 += __shfl_xor_sync(0xFFFFFFFF, s0, 2);
        s1 += __shfl_xor_sync(0xFFFFFFFF, s1, 1);
        s1 += __shfl_xor_sync(0xFFFFFFFF, s1, 2);
        if ((lane & 3) == 0) {
            int r0 = wm * 64 + mt * 16 + (lane >> 2);
            red[r0 * 4 + wn] = s0;
            red[(r0 + 8) * 4 + wn] = s1;
        }
    }
    __syncthreads();
    if (tid < 128) {
        float s = red[tid * 4] + red[tid * 4 + 1] + red[tid * 4 + 2] + red[tid * 4 + 3];
        atomicAdd(&energy[rowBase + tid], s);
    }
}

// ---------------------------------------------------------------------------
// 5) masked softmax per batch row (0/1 multiply-mask semantics)
// ---------------------------------------------------------------------------
__global__ void softmax_kernel(const float* __restrict__ energy,
                               const int* __restrict__ x_lens,
                               float* __restrict__ att) {
    int b = blockIdx.x;
    int tid = threadIdx.x;
    int len = x_lens[b];
    __shared__ float sh[256];

    float e[8];
    float mx = -1e30f;
    #pragma unroll
    for (int j = 0; j < 8; j++) {
        int t = tid + j * 256;
        float val = energy[b * TT + t];
        val = (t < len) ? val : 0.0f;
        e[j] = val;
        mx = fmaxf(mx, val);
    }
    sh[tid] = mx;
    __syncthreads();
    for (int s = 128; s > 0; s >>= 1) {
        if (tid < s) sh[tid] = fmaxf(sh[tid], sh[tid + s]);
        __syncthreads();
    }
    mx = sh[0];
    __syncthreads();

    float sum = 0.0f;
    #pragma unroll
    for (int j = 0; j < 8; j++) {
        e[j] = expf(e[j] - mx);
        sum += e[j];
    }
    sh[tid] = sum;
    __syncthreads();
    for (int s = 128; s > 0; s >>= 1) {
        if (tid < s) sh[tid] += sh[tid + s];
        __syncthreads();
    }
    float inv = 1.0f / sh[0];

    #pragma unroll
    for (int j = 0; j < 8; j++) {
        int t = tid + j * 256;
        att[b * TT + t] = e[j] * inv;
    }
}

// ---------------------------------------------------------------------------
// 6) context[b,e] = sum_t att[b,t] * enc[b,t,e]
// ---------------------------------------------------------------------------
__global__ void context_kernel(const float* __restrict__ enc,
                               const float* __restrict__ att,
                               float* __restrict__ ctx) {
    int b = blockIdx.x;
    int t0 = blockIdx.y * 128;
    int tid = threadIdx.x;

    __shared__ float ws[128];
    if (tid < 128) ws[tid] = att[b * TT + t0 + tid];
    __syncthreads();

    float acc[4] = {0.0f, 0.0f, 0.0f, 0.0f};
    for (int t = 0; t < 128; t++) {
        float w = ws[t];
        const float* row = enc + ((size_t)(b * TT + t0 + t)) * EE;
        #pragma unroll
        for (int j = 0; j < 4; j++)
            acc[j] = fmaf(w, row[tid + j * 256], acc[j]);
    }
    #pragma unroll
    for (int j = 0; j < 4; j++)
        atomicAdd(&ctx[b * EE + tid + j * 256], acc[j]);
}

// ---------------------------------------------------------------------------
// launch
// ---------------------------------------------------------------------------
extern "C" void kernel_launch(void* const* d_in, const int* in_sizes, int n_in,
                              void* d_out, int out_size) {
    const float* enc_out = (const float*)d_in[0];
    const int*   x_lens  = (const int*)  d_in[1];
    const float* dec_out = (const float*)d_in[2];
    const float* W_enc   = (const float*)d_in[4];
    const float* b_enc   = (const float*)d_in[5];
    const float* W_dec   = (const float*)d_in[6];
    const float* v       = (const float*)d_in[7];

    float* out = (float*)d_out;
    float* ctx = out;
    float* att = out + BB * EE;

    float* dp;
    float* energy;
    cudaGetSymbolAddress((void**)&dp, g_dp);
    cudaGetSymbolAddress((void**)&energy, g_energy);

    cudaFuncSetAttribute(energy_gemm_mma,
                         cudaFuncAttributeMaxDynamicSharedMemorySize, GEMM_SMEM);

    zero_kernel<<<(BB * TT + 255) / 256, 256>>>(energy, ctx);
    split_enc_kernel<<<MROWS, 256>>>(enc_out);
    split_w_kernel<<<dim3(32, 32), dim3(32, 8)>>>(W_enc);
    dec_proj_kernel<<<128, 256>>>(dec_out, W_dec, b_enc, dp);

    dim3 grid(AA / 128, MROWS / 128);  // (8, 512)
    energy_gemm_mma<<<grid, 256, GEMM_SMEM>>>(dp, v, energy);

    softmax_kernel<<<BB, 256>>>(energy, x_lens, att);

    dim3 cgrid(BB, 16);
    context_kernel<<<cgrid, 256>>>(enc_out, att, ctx);
}

// round 11
// speedup vs baseline: 3.0063x; 1.2741x over previous
#include <cuda_runtime.h>
#include <cuda_bf16.h>
#include <math.h>
#include <stdint.h>

// Problem constants
#define BB 32
#define TT 2048
#define EE 1024
#define AA 1024
#define DD 1024
#define MROWS (BB * TT)   // 65536

// ---------------------------------------------------------------------------
// Scratch (__device__ globals; no cudaMalloc allowed)
// ---------------------------------------------------------------------------
__device__ __nv_bfloat16 g_encsplit[(size_t)MROWS * 2048]; // [row, 0:1024]=hi, [1024:2048]=lo
__device__ __nv_bfloat16 g_wsplit[(size_t)AA * 2048];      // [a, 0:1024]=W^T hi, [1024:2048]=lo
__device__ float g_dp[BB * AA];                            // dec_proj + b_enc
__device__ float g_energy[BB * TT];                        // pre-softmax energy

// ---------------------------------------------------------------------------
// PTX helpers (base-target-safe only: cp.async / ldmatrix / mma.sync)
// ---------------------------------------------------------------------------
__device__ __forceinline__ uint32_t smem_u32(const void* p) {
    uint32_t a;
    asm("{ .reg .u64 t; cvta.to.shared.u64 t, %1; cvt.u32.u64 %0, t; }" : "=r"(a) : "l"(p));
    return a;
}

__device__ __forceinline__ void cp_async16(uint32_t dst, const void* src) {
    asm volatile("cp.async.cg.shared.global [%0], [%1], 16;\n" :: "r"(dst), "l"(src));
}
#define CP_COMMIT() asm volatile("cp.async.commit_group;\n" ::: "memory")
#define CP_WAIT1()  asm volatile("cp.async.wait_group 1;\n" ::: "memory")
#define CP_WAIT0()  asm volatile("cp.async.wait_group 0;\n" ::: "memory")

__device__ __forceinline__ void ldm_x4(uint32_t& r0, uint32_t& r1, uint32_t& r2, uint32_t& r3,
                                       uint32_t addr) {
    asm volatile("ldmatrix.sync.aligned.m8n8.x4.shared.b16 {%0,%1,%2,%3}, [%4];"
                 : "=r"(r0), "=r"(r1), "=r"(r2), "=r"(r3) : "r"(addr));
}

__device__ __forceinline__ void mma_bf16(float* c, uint32_t a0, uint32_t a1, uint32_t a2,
                                         uint32_t a3, uint32_t b0, uint32_t b1) {
    asm volatile(
        "mma.sync.aligned.m16n8k16.row.col.f32.bf16.bf16.f32 "
        "{%0,%1,%2,%3}, {%4,%5,%6,%7}, {%8,%9}, {%0,%1,%2,%3};"
        : "+f"(c[0]), "+f"(c[1]), "+f"(c[2]), "+f"(c[3])
        : "r"(a0), "r"(a1), "r"(a2), "r"(a3), "r"(b0), "r"(b1));
}

// ---------------------------------------------------------------------------
// 0) zero energy + ctx; seed dp with b_enc
// ---------------------------------------------------------------------------
__global__ void zero_kernel(float* __restrict__ energy, float* __restrict__ ctx,
                            float* __restrict__ dp, const float* __restrict__ b_enc) {
    int i = blockIdx.x * blockDim.x + threadIdx.x;
    if (i < BB * TT) energy[i] = 0.0f;
    if (i < BB * EE) ctx[i] = 0.0f;
    if (i < BB * AA) dp[i] = b_enc[i & (AA - 1)];
}

// ---------------------------------------------------------------------------
// 1) split enc_out into bf16 hi/lo
// ---------------------------------------------------------------------------
__global__ void split_enc_kernel(const float* __restrict__ enc) {
    int row = blockIdx.x;
    int tid = threadIdx.x;  // 0..255
    float4 x = ((const float4*)(enc + (size_t)row * EE))[tid];
    union { __nv_bfloat16 h[4]; uint2 u; } hi, lo;
    float xs[4] = {x.x, x.y, x.z, x.w};
    #pragma unroll
    for (int k = 0; k < 4; k++) {
        __nv_bfloat16 h = __float2bfloat16(xs[k]);
        hi.h[k] = h;
        lo.h[k] = __float2bfloat16(xs[k] - __bfloat162float(h));
    }
    __nv_bfloat16* base = g_encsplit + (size_t)row * 2048;
    *(uint2*)(base + tid * 4)        = hi.u;
    *(uint2*)(base + 1024 + tid * 4) = lo.u;
}

// ---------------------------------------------------------------------------
// 2) split + transpose W_enc: g_wsplit[a, e] = bf16split(W_enc[e, a])
// ---------------------------------------------------------------------------
__global__ void split_w_kernel(const float* __restrict__ W) {
    __shared__ float tile[32][33];
    int e0 = blockIdx.x * 32, a0 = blockIdx.y * 32;
    int tx = threadIdx.x, ty = threadIdx.y;  // 32 x 8
    #pragma unroll
    for (int k = 0; k < 4; k++) {
        int e = ty + k * 8;
        tile[e][tx] = W[(size_t)(e0 + e) * AA + a0 + tx];
    }
    __syncthreads();
    #pragma unroll
    for (int k = 0; k < 4; k++) {
        int a = ty + k * 8;
        float val = tile[tx][a];
        __nv_bfloat16 h = __float2bfloat16(val);
        __nv_bfloat16 l = __float2bfloat16(val - __bfloat162float(h));
        __nv_bfloat16* base = g_wsplit + (size_t)(a0 + a) * 2048;
        base[e0 + tx] = h;
        base[1024 + e0 + tx] = l;
    }
}

// ---------------------------------------------------------------------------
// 3) dec_proj: dp[b,a] += sum_d dec[b,d] * W_dec[d,a]   (dp pre-seeded b_enc)
//    grid (8 a-groups, 32 d-groups), 256 threads
// ---------------------------------------------------------------------------
__global__ void dec_proj_kernel(const float* __restrict__ dec,
                                const float* __restrict__ Wdec,
                                float* __restrict__ dp) {
    int a0 = blockIdx.x * 128;
    int d0 = blockIdx.y * 32;
    __shared__ float wsm[32][128];
    __shared__ float dsm[32][32];
    int tid = threadIdx.x;
    for (int i = tid; i < 32 * 128; i += 256) {
        int d = i >> 7, a = i & 127;
        wsm[d][a] = Wdec[(size_t)(d0 + d) * AA + a0 + a];
    }
    for (int i = tid; i < 32 * 32; i += 256) {
        int b = i >> 5, d = i & 31;
        dsm[b][d] = dec[b * DD + d0 + d];
    }
    __syncthreads();
    int a = tid & 127;
    int b0 = (tid >> 7) * 16;
    #pragma unroll
    for (int bi = 0; bi < 16; bi++) {
        int b = b0 + bi;
        float s = 0.0f;
        #pragma unroll
        for (int d = 0; d < 32; d++)
            s = fmaf(dsm[b][d], wsm[d][a], s);
        atomicAdd(&dp[b * AA + a0 + a], s);
    }
}

// ---------------------------------------------------------------------------
// 4) mma.sync bf16-split GEMM + tanh + v-dot -> energy
//    CTA 128x128, 8 warps (2x4), warp 64x32, real-K slabs of 32.
//    Per slab stage holds {A_hi, A_lo, B_hi, B_lo}; computes
//    A_hi*B_hi + A_hi*B_lo + A_lo*B_hi with one smem residency of A_hi.
// ---------------------------------------------------------------------------
#define ROWB 80                  // padded smem row stride (bytes) for 32 bf16
#define TILE_SZ (128 * ROWB)     // 10240
#define STG (4 * TILE_SZ)        // 40960 per stage
#define NSTAGE 2
#define GEMM_SMEM (NSTAGE * STG) // 81920
#define NCHUNK 32

__device__ __forceinline__ void load_stage(int chunk, uint32_t st,
                                           int rowBase, int colBase, int tid) {
    const char* aHi = (const char*)g_encsplit + (size_t)rowBase * 4096 + (size_t)chunk * 64;
    const char* bHi = (const char*)g_wsplit  + (size_t)colBase * 4096 + (size_t)chunk * 64;
    const char* srcs[4] = { aHi, aHi + 2048, bHi, bHi + 2048 };
    #pragma unroll
    for (int t4 = 0; t4 < 4; t4++) {
        const char* src = srcs[t4];
        uint32_t dstBase = st + t4 * TILE_SZ;
        #pragma unroll
        for (int k = 0; k < 2; k++) {
            int idx = tid + k * 256;
            int r = idx >> 2, sg = idx & 3;
            cp_async16(dstBase + r * ROWB + sg * 16, src + (size_t)r * 4096 + sg * 16);
        }
    }
}

__global__ __launch_bounds__(256, 2)
void energy_gemm_mma(const float* __restrict__ dp,
                     const float* __restrict__ v,
                     float* __restrict__ energy) {
    extern __shared__ char smem[];
    uint32_t sb = smem_u32(smem);
    int tid = threadIdx.x;
    int lane = tid & 31;
    int w = tid >> 5;
    int wm = w >> 2;          // 0..1  (64 rows each)
    int wn = w & 3;           // 0..3  (32 cols each)
    int rowBase = blockIdx.y * 128;
    int colBase = blockIdx.x * 128;
    int b = rowBase >> 11;

    float acc[4][4][4];       // [mt][nt][reg]
    #pragma unroll
    for (int i = 0; i < 4; i++)
        #pragma unroll
        for (int jj = 0; jj < 4; jj++)
            #pragma unroll
            for (int r = 0; r < 4; r++) acc[i][jj][r] = 0.0f;

    load_stage(0, sb, rowBase, colBase, tid);
    CP_COMMIT();
    load_stage(1, sb + STG, rowBase, colBase, tid);
    CP_COMMIT();

    // ldmatrix base offsets (relative to tile base)
    uint32_t aAddrOff = (uint32_t)((wm * 64 + (lane & 15)) * ROWB + ((lane >> 4) & 1) * 16);
    uint32_t bAddrOff = (uint32_t)((wn * 32 + (lane & 7) + ((lane >> 4) & 1) * 8) * ROWB
                                   + ((lane >> 3) & 1) * 16);

    for (int i = 0; i < NCHUNK; i++) {
        if (i < NCHUNK - 1) CP_WAIT1(); else CP_WAIT0();
        __syncthreads();
        uint32_t st = sb + (i & 1) * STG;
        uint32_t Ahi = st;
        uint32_t Alo = st + TILE_SZ;
        uint32_t Bhi = st + 2 * TILE_SZ;
        uint32_t Blo = st + 3 * TILE_SZ;

        #pragma unroll
        for (int ks = 0; ks < 2; ks++) {
            uint32_t af[4][4];
            uint32_t bh[2][4], bl[2][4];
            #pragma unroll
            for (int mt = 0; mt < 4; mt++)
                ldm_x4(af[mt][0], af[mt][1], af[mt][2], af[mt][3],
                       Ahi + aAddrOff + mt * 16 * ROWB + ks * 32);
            #pragma unroll
            for (int np = 0; np < 2; np++)
                ldm_x4(bh[np][0], bh[np][1], bh[np][2], bh[np][3],
                       Bhi + bAddrOff + np * 16 * ROWB + ks * 32);
            #pragma unroll
            for (int np = 0; np < 2; np++)
                ldm_x4(bl[np][0], bl[np][1], bl[np][2], bl[np][3],
                       Blo + bAddrOff + np * 16 * ROWB + ks * 32);
            // A_hi * B_hi
            #pragma unroll
            for (int mt = 0; mt < 4; mt++)
                #pragma unroll
                for (int nt = 0; nt < 4; nt++)
                    mma_bf16(acc[mt][nt], af[mt][0], af[mt][1], af[mt][2], af[mt][3],
                             bh[nt >> 1][(nt & 1) * 2 + 0], bh[nt >> 1][(nt & 1) * 2 + 1]);
            // A_hi * B_lo
            #pragma unroll
            for (int mt = 0; mt < 4; mt++)
                #pragma unroll
                for (int nt = 0; nt < 4; nt++)
                    mma_bf16(acc[mt][nt], af[mt][0], af[mt][1], af[mt][2], af[mt][3],
                             bl[nt >> 1][(nt & 1) * 2 + 0], bl[nt >> 1][(nt & 1) * 2 + 1]);
            // A_lo * B_hi  (reuse af registers)
            #pragma unroll
            for (int mt = 0; mt < 4; mt++)
                ldm_x4(af[mt][0], af[mt][1], af[mt][2], af[mt][3],
                       Alo + aAddrOff + mt * 16 * ROWB + ks * 32);
            #pragma unroll
            for (int mt = 0; mt < 4; mt++)
                #pragma unroll
                for (int nt = 0; nt < 4; nt++)
                    mma_bf16(acc[mt][nt], af[mt][0], af[mt][1], af[mt][2], af[mt][3],
                             bh[nt >> 1][(nt & 1) * 2 + 0], bh[nt >> 1][(nt & 1) * 2 + 1]);
        }
        __syncthreads();
        if (i + 2 < NCHUNK) {
            load_stage(i + 2, st, rowBase, colBase, tid);
            CP_COMMIT();
        }
    }
    __syncthreads();

    // Epilogue: s[row] = sum_col v[col] * tanh(acc + dp[col]); quad shfl-reduce
    float* red = (float*)smem;    // [128][4]
    #pragma unroll
    for (int mt = 0; mt < 4; mt++) {
        float s0 = 0.0f, s1 = 0.0f;
        #pragma unroll
        for (int nt = 0; nt < 4; nt++) {
            int col = colBase + wn * 32 + nt * 8 + (lane & 3) * 2;
            float d0 = dp[b * AA + col], d1 = dp[b * AA + col + 1];
            float v0 = v[col], v1 = v[col + 1];
            s0 = fmaf(v0, tanhf(acc[mt][nt][0] + d0), s0);
            s0 = fmaf(v1, tanhf(acc[mt][nt][1] + d1), s0);
            s1 = fmaf(v0, tanhf(acc[mt][nt][2] + d0), s1);
            s1 = fmaf(v1, tanhf(acc[mt][nt][3] + d1), s1);
        }
        s0 += __shfl_xor_sync(0xFFFFFFFF, s0, 1);
        s0 += __shfl_xor_sync(0xFFFFFFFF, s0, 2);
        s1 += __shfl_xor_sync(0xFFFFFFFF, s1, 1);
        s1 += __shfl_xor_sync(0xFFFFFFFF, s1, 2);
        if ((lane & 3) == 0) {
            int r0 = wm * 64 + mt * 16 + (lane >> 2);
            red[r0 * 4 + wn] = s0;
            red[(r0 + 8) * 4 + wn] = s1;
        }
    }
    __syncthreads();
    if (tid < 128) {
        float s = red[tid * 4] + red[tid * 4 + 1] + red[tid * 4 + 2] + red[tid * 4 + 3];
        atomicAdd(&energy[rowBase + tid], s);
    }
}

// ---------------------------------------------------------------------------
// 5) masked softmax per batch row (0/1 multiply-mask semantics)
// ---------------------------------------------------------------------------
__global__ void softmax_kernel(const float* __restrict__ energy,
                               const int* __restrict__ x_lens,
                               float* __restrict__ att) {
    int b = blockIdx.x;
    int tid = threadIdx.x;
    int len = x_lens[b];
    __shared__ float sh[256];

    float e[8];
    float mx = -1e30f;
    #pragma unroll
    for (int j = 0; j < 8; j++) {
        int t = tid + j * 256;
        float val = energy[b * TT + t];
        val = (t < len) ? val : 0.0f;
        e[j] = val;
        mx = fmaxf(mx, val);
    }
    sh[tid] = mx;
    __syncthreads();
    for (int s = 128; s > 0; s >>= 1) {
        if (tid < s) sh[tid] = fmaxf(sh[tid], sh[tid + s]);
        __syncthreads();
    }
    mx = sh[0];
    __syncthreads();

    float sum = 0.0f;
    #pragma unroll
    for (int j = 0; j < 8; j++) {
        e[j] = expf(e[j] - mx);
        sum += e[j];
    }
    sh[tid] = sum;
    __syncthreads();
    for (int s = 128; s > 0; s >>= 1) {
        if (tid < s) sh[tid] += sh[tid + s];
        __syncthreads();
    }
    float inv = 1.0f / sh[0];

    #pragma unroll
    for (int j = 0; j < 8; j++) {
        int t = tid + j * 256;
        att[b * TT + t] = e[j] * inv;
    }
}

// ---------------------------------------------------------------------------
// 6) context[b,e] = sum_t att[b,t] * enc[b,t,e]
// ---------------------------------------------------------------------------
__global__ void context_kernel(const float* __restrict__ enc,
                               const float* __restrict__ att,
                               float* __restrict__ ctx) {
    int b = blockIdx.x;
    int t0 = blockIdx.y * 128;
    int tid = threadIdx.x;

    __shared__ float ws[128];
    if (tid < 128) ws[tid] = att[b * TT + t0 + tid];
    __syncthreads();

    float acc[4] = {0.0f, 0.0f, 0.0f, 0.0f};
    for (int t = 0; t < 128; t++) {
        float w = ws[t];
        const float* row = enc + ((size_t)(b * TT + t0 + t)) * EE;
        #pragma unroll
        for (int j = 0; j < 4; j++)
            acc[j] = fmaf(w, row[tid + j * 256], acc[j]);
    }
    #pragma unroll
    for (int j = 0; j < 4; j++)
        atomicAdd(&ctx[b * EE + tid + j * 256], acc[j]);
}

// ---------------------------------------------------------------------------
// launch
// ---------------------------------------------------------------------------
extern "C" void kernel_launch(void* const* d_in, const int* in_sizes, int n_in,
                              void* d_out, int out_size) {
    const float* enc_out = (const float*)d_in[0];
    const int*   x_lens  = (const int*)  d_in[1];
    const float* dec_out = (const float*)d_in[2];
    const float* W_enc   = (const float*)d_in[4];
    const float* b_enc   = (const float*)d_in[5];
    const float* W_dec   = (const float*)d_in[6];
    const float* v       = (const float*)d_in[7];

    float* out = (float*)d_out;
    float* ctx = out;
    float* att = out + BB * EE;

    float* dp;
    float* energy;
    cudaGetSymbolAddress((void**)&dp, g_dp);
    cudaGetSymbolAddress((void**)&energy, g_energy);

    cudaFuncSetAttribute(energy_gemm_mma,
                         cudaFuncAttributeMaxDynamicSharedMemorySize, GEMM_SMEM);

    zero_kernel<<<(BB * TT + 255) / 256, 256>>>(energy, ctx, dp, b_enc);
    split_enc_kernel<<<MROWS, 256>>>(enc_out);
    split_w_kernel<<<dim3(32, 32), dim3(32, 8)>>>(W_enc);
    dec_proj_kernel<<<dim3(8, 32), 256>>>(dec_out, W_dec, dp);

    dim3 grid(AA / 128, MROWS / 128);  // (8, 512)
    energy_gemm_mma<<<grid, 256, GEMM_SMEM>>>(dp, v, energy);

    softmax_kernel<<<BB, 256>>>(energy, x_lens, att);

    dim3 cgrid(BB, 16);
    context_kernel<<<cgrid, 256>>>(enc_out, att, ctx);
}